// round 2
// baseline (speedup 1.0000x reference)
#include <cuda_runtime.h>
#include <math.h>

#define H     128
#define NB    16384
#define NPG   26
#define EPG   52
#define NCL   7
#define NTOT  (NB*NPG)      // 425984
#define NEDGE (NB*EPG)      // 851968

// ------------- scratch: device globals (no runtime allocation) -------------
__device__ float g_h[NTOT*H];        // node features (in-place per layer)
__device__ float g_mean[NTOT*H];     // neighbor means
__device__ float g_slog[NTOT*NCL];   // assignment logits
__device__ float g_x2[NB*NCL*H];     // pooled cluster features (in-place)
__device__ float g_pm[NB*H];         // per-graph mean of clusters
__device__ float g_linkpart[NB];
__device__ float g_entpart[NB];

// ---------------- K1: atom encoder ----------------
// grid NTOT/32, 128 threads. h[n,:] = sum_f emb[f, x[n,f], :]
__global__ void k_encode(const int* __restrict__ x, const float* __restrict__ emb) {
    const int tid = threadIdx.x;
    const int n0  = blockIdx.x * 32;
    __shared__ int sx[32 * 9];
    for (int i = tid; i < 32 * 9; i += 128) sx[i] = x[(size_t)n0 * 9 + i];
    __syncthreads();
    for (int nn = 0; nn < 32; nn++) {
        float acc = 0.f;
        #pragma unroll
        for (int f = 0; f < 9; f++) {
            int v = sx[nn * 9 + f];
            acc += emb[((size_t)f * 119 + v) * 128 + tid];
        }
        g_h[(size_t)(n0 + nn) * 128 + tid] = acc;
    }
}

// ---------------- K2: per-graph neighbor-mean aggregation ----------------
// grid NB, 128 threads (thread = feature column)
__global__ void k_agg(const int* __restrict__ ei) {
    __shared__ float sh [NPG * H];
    __shared__ float sag[NPG * H];
    __shared__ int   ssrc[EPG], sdst[EPG];
    __shared__ int   degi[NPG];
    __shared__ float rdeg[NPG];
    const int g = blockIdx.x, tid = threadIdx.x;
    const float* hg = g_h + (size_t)g * NPG * H;
    for (int i = tid; i < NPG * H; i += 128) { sh[i] = hg[i]; sag[i] = 0.f; }
    if (tid < EPG) {
        ssrc[tid] = ei[(size_t)g * EPG + tid]          - g * NPG;
        sdst[tid] = ei[(size_t)NEDGE + g * EPG + tid]  - g * NPG;
    }
    if (tid < NPG) degi[tid] = 0;
    __syncthreads();
    if (tid < EPG) atomicAdd(&degi[sdst[tid]], 1);
    __syncthreads();
    if (tid < NPG) rdeg[tid] = 1.f / fmaxf((float)degi[tid], 1.f);
    // each thread owns its own column -> race-free serial edge loop
    for (int e = 0; e < EPG; e++)
        sag[sdst[e] * H + tid] += sh[ssrc[e] * H + tid];
    __syncthreads();
    float* mg = g_mean + (size_t)g * NPG * H;
    for (int i = tid; i < NPG * H; i += 128) mg[i] = sag[i] * rdeg[i >> 7];
}

// ---------------- K3: fused SGEMM + bias + BN + (ReLU) + residual, in place ----------------
// Out(rows) = bn( [Am_row | Ah_row] @ [Wl; Wr] + bl ) (+relu) + Ah_row
// POOLED=0: Am=g_mean, Ah=g_h, mean row = row.  POOLED=1: Am=g_pm, Ah=g_x2, mean row = row/7.
template<int RELU, int POOLED>
__global__ __launch_bounds__(256)
void k_gemm(const float* __restrict__ Wl, const float* __restrict__ Wr,
            const float* __restrict__ bl,
            const float* __restrict__ bng, const float* __restrict__ bnb,
            const float* __restrict__ bnm, const float* __restrict__ bnv)
{
    const float* Am = POOLED ? g_pm : g_mean;
    float*       Ah = POOLED ? g_x2 : g_h;

    __shared__ float As[16][128];     // [k][m]
    __shared__ float Bs[16][128];     // [k][n]
    __shared__ float s_scale[128], s_shift[128];

    const int tid  = threadIdx.x;
    const int row0 = blockIdx.x * 128;
    if (tid < 128) {
        float sc = bng[tid] / sqrtf(bnv[tid] + 1e-5f);
        s_scale[tid] = sc;
        s_shift[tid] = bnb[tid] + sc * (bl[tid] - bnm[tid]);
    }
    const int tx = tid & 15, ty = tid >> 4;
    const int m0 = ty * 8, n0 = tx * 8;

    float acc[8][8];
    #pragma unroll
    for (int i = 0; i < 8; i++)
        #pragma unroll
        for (int j = 0; j < 8; j++) acc[i][j] = 0.f;

    #pragma unroll 1
    for (int kc = 0; kc < 16; kc++) {
        const int kbase = kc * 16;
        // --- load A chunk: 128 rows x 16 k = 512 float4 ---
        #pragma unroll
        for (int r = 0; r < 2; r++) {
            int la   = tid + r * 256;
            int arow = la >> 2;          // 0..127
            int kq   = la & 3;           // float4 slot within 16-k chunk
            int grow = row0 + arow;
            int gk   = kbase + kq * 4;
            float4 v;
            if (gk < 128) {
                int mrow = POOLED ? (grow / 7) : grow;
                v = *(const float4*)(Am + (size_t)mrow * 128 + gk);
            } else {
                v = *(const float4*)(Ah + (size_t)grow * 128 + (gk - 128));
            }
            As[kq * 4 + 0][arow] = v.x;
            As[kq * 4 + 1][arow] = v.y;
            As[kq * 4 + 2][arow] = v.z;
            As[kq * 4 + 3][arow] = v.w;
        }
        // --- load B chunk: 16 k-rows x 128 cols = 512 float4 ---
        #pragma unroll
        for (int r = 0; r < 2; r++) {
            int lb   = tid + r * 256;
            int krow = lb >> 5;          // 0..15
            int nq   = lb & 31;
            int gk   = kbase + krow;
            const float* src = (gk < 128) ? (Wl + (size_t)gk * 128)
                                          : (Wr + (size_t)(gk - 128) * 128);
            *(float4*)&Bs[krow][nq * 4] = *(const float4*)(src + nq * 4);
        }
        __syncthreads();
        #pragma unroll
        for (int kk = 0; kk < 16; kk++) {
            float a[8], b[8];
            *(float4*)(a)     = *(const float4*)&As[kk][m0];
            *(float4*)(a + 4) = *(const float4*)&As[kk][m0 + 4];
            *(float4*)(b)     = *(const float4*)&Bs[kk][n0];
            *(float4*)(b + 4) = *(const float4*)&Bs[kk][n0 + 4];
            #pragma unroll
            for (int i = 0; i < 8; i++)
                #pragma unroll
                for (int j = 0; j < 8; j++)
                    acc[i][j] += a[i] * b[j];
        }
        __syncthreads();
    }
    // --- epilogue: bias+bn folded, relu, residual, in-place write ---
    float sc[8], sf[8];
    #pragma unroll
    for (int j = 0; j < 8; j++) { sc[j] = s_scale[n0 + j]; sf[j] = s_shift[n0 + j]; }
    #pragma unroll
    for (int i = 0; i < 8; i++) {
        int grow = row0 + m0 + i;
        float* orow = Ah + (size_t)grow * 128 + n0;
        float4 r0 = *(const float4*)orow;
        float4 r1 = *(const float4*)(orow + 4);
        float res[8] = {r0.x, r0.y, r0.z, r0.w, r1.x, r1.y, r1.z, r1.w};
        float o[8];
        #pragma unroll
        for (int j = 0; j < 8; j++) {
            float v = acc[i][j] * sc[j] + sf[j];
            if (RELU) v = fmaxf(v, 0.f);
            o[j] = v + res[j];
        }
        *(float4*)orow       = make_float4(o[0], o[1], o[2], o[3]);
        *(float4*)(orow + 4) = make_float4(o[4], o[5], o[6], o[7]);
    }
}

// ---------------- K4: assignment logits (warp per node) ----------------
// slog[n,c] = mean[n]@aWl[:,c] + h[n]@aWr[:,c] + abl[c]
__global__ void k_slog(const float* __restrict__ aWl, const float* __restrict__ abl,
                       const float* __restrict__ aWr) {
    __shared__ float sWl[128 * NCL], sWr[128 * NCL];
    const int tid = threadIdx.x;  // 256
    for (int i = tid; i < 128 * NCL; i += 256) { sWl[i] = aWl[i]; sWr[i] = aWr[i]; }
    __syncthreads();
    const int warp = tid >> 5, lane = tid & 31;
    const int gw = blockIdx.x * 8 + warp;
    const int stride = gridDim.x * 8;
    for (int n = gw; n < NTOT; n += stride) {
        const float* mrow = g_mean + (size_t)n * 128;
        const float* hrow = g_h    + (size_t)n * 128;
        float m[4], h[4];
        #pragma unroll
        for (int j = 0; j < 4; j++) { m[j] = mrow[lane + 32 * j]; h[j] = hrow[lane + 32 * j]; }
        #pragma unroll
        for (int c = 0; c < NCL; c++) {
            float p = 0.f;
            #pragma unroll
            for (int j = 0; j < 4; j++) {
                int k = lane + 32 * j;
                p += m[j] * sWl[k * NCL + c] + h[j] * sWr[k * NCL + c];
            }
            #pragma unroll
            for (int off = 16; off > 0; off >>= 1)
                p += __shfl_down_sync(0xffffffffu, p, off);
            if (lane == 0) g_slog[(size_t)n * NCL + c] = p + abl[c];
        }
    }
}

// ---------------- K5: per-graph softmax + pooling + losses ----------------
__global__ void k_pool(const int* __restrict__ ei) {
    __shared__ float sh[NPG * H];
    __shared__ float sd[NPG * NCL];
    __shared__ float adj[NPG * NPG];
    __shared__ float red[128], red2[128];
    const int g = blockIdx.x, tid = threadIdx.x;  // 128
    const float* hg = g_h + (size_t)g * NPG * H;
    for (int i = tid; i < NPG * H; i += 128) sh[i] = hg[i];
    for (int i = tid; i < NPG * NPG; i += 128) adj[i] = 0.f;
    __syncthreads();
    float ent_local = 0.f;
    if (tid < NPG) {
        const float* sl = g_slog + ((size_t)g * NPG + tid) * NCL;
        float v[NCL];
        float mx = -1e30f;
        #pragma unroll
        for (int c = 0; c < NCL; c++) { v[c] = sl[c]; mx = fmaxf(mx, v[c]); }
        float s = 0.f;
        #pragma unroll
        for (int c = 0; c < NCL; c++) { v[c] = expf(v[c] - mx); s += v[c]; }
        float inv = 1.f / s;
        #pragma unroll
        for (int c = 0; c < NCL; c++) {
            float p = v[c] * inv;
            sd[tid * NCL + c] = p;
            ent_local += -p * logf(p + 1e-15f);
        }
    }
    if (tid < EPG) {
        int s = ei[(size_t)g * EPG + tid]         - g * NPG;
        int d = ei[(size_t)NEDGE + g * EPG + tid] - g * NPG;
        atomicAdd(&adj[s * NPG + d], 1.f);
    }
    __syncthreads();
    // x2[c,:] = sum_n sd[n,c] * h[n,:]
    float* x2g = g_x2 + (size_t)g * NCL * H;
    #pragma unroll
    for (int c = 0; c < NCL; c++) {
        float a = 0.f;
        #pragma unroll
        for (int n = 0; n < NPG; n++) a += sd[n * NCL + c] * sh[n * 128 + tid];
        x2g[c * 128 + tid] = a;
    }
    // link loss partial: sum over pairs of (adj - s s^T)^2
    float link_local = 0.f;
    for (int p = tid; p < NPG * NPG; p += 128) {
        int n = p / NPG, m = p - NPG * n;
        float ss = 0.f;
        #pragma unroll
        for (int c = 0; c < NCL; c++) ss += sd[n * NCL + c] * sd[m * NCL + c];
        float d = adj[p] - ss;
        link_local += d * d;
    }
    red[tid] = link_local; red2[tid] = ent_local;
    __syncthreads();
    for (int s = 64; s > 0; s >>= 1) {
        if (tid < s) { red[tid] += red[tid + s]; red2[tid] += red2[tid + s]; }
        __syncthreads();
    }
    if (tid == 0) { g_linkpart[g] = red[0]; g_entpart[g] = red2[0]; }
}

// ---------------- K6: per-graph mean of clusters ----------------
__global__ void k_pmean() {
    int idx = blockIdx.x * 256 + threadIdx.x;     // NB*128 total
    int g = idx >> 7, col = idx & 127;
    const float* xg = g_x2 + (size_t)g * NCL * H + col;
    float a = 0.f;
    #pragma unroll
    for (int c = 0; c < NCL; c++) a += xg[c * 128];
    g_pm[idx] = a * (1.f / 7.f);
}

// ---------------- K7: readout ----------------
__global__ void k_readout(const float* __restrict__ linW, const float* __restrict__ linb,
                          float* __restrict__ out) {
    const int g = blockIdx.x, tid = threadIdx.x;  // 128
    const float* xg = g_x2 + (size_t)g * NCL * H;
    float v = 0.f;
    #pragma unroll
    for (int c = 0; c < NCL; c++) v += xg[c * 128 + tid];
    v *= (1.f / 7.f);
    __shared__ float red[128];
    red[tid] = v * linW[tid];
    __syncthreads();
    for (int s = 64; s > 0; s >>= 1) {
        if (tid < s) red[tid] += red[tid + s];
        __syncthreads();
    }
    if (tid == 0) out[g] = 1.f / (1.f + expf(-(red[0] + linb[0])));
}

// ---------------- K8: deterministic loss reduction ----------------
__global__ void k_reduce(float* __restrict__ out) {
    __shared__ float s1[1024], s2[1024];
    const int tid = threadIdx.x;
    float a = 0.f, b = 0.f;
    for (int i = tid; i < NB; i += 1024) { a += g_linkpart[i]; b += g_entpart[i]; }
    s1[tid] = a; s2[tid] = b;
    __syncthreads();
    for (int s = 512; s > 0; s >>= 1) {
        if (tid < s) { s1[tid] += s1[tid + s]; s2[tid] += s2[tid + s]; }
        __syncthreads();
    }
    if (tid == 0) {
        out[NB]     = sqrtf(s1[0]) / 11075584.f;   // nb * 26 * 26
        out[NB + 1] = s2[0] / (float)NTOT;
    }
}

extern "C" void kernel_launch(void* const* d_in, const int* in_sizes, int n_in,
                              void* d_out, int out_size) {
    (void)in_sizes; (void)n_in; (void)out_size;
    const int*   x    = (const int*)  d_in[0];
    const int*   ei   = (const int*)  d_in[1];
    // d_in[2] = batch_idx (unused; structure is implicit)
    const float* emb  = (const float*)d_in[3];
    const float* cWl  = (const float*)d_in[4];
    const float* cbl  = (const float*)d_in[5];
    const float* cWr  = (const float*)d_in[6];
    const float* bng  = (const float*)d_in[7];
    const float* bnb  = (const float*)d_in[8];
    const float* bnm  = (const float*)d_in[9];
    const float* bnv  = (const float*)d_in[10];
    const float* aWl  = (const float*)d_in[11];
    const float* abl  = (const float*)d_in[12];
    const float* aWr  = (const float*)d_in[13];
    const float* linW = (const float*)d_in[14];
    const float* linb = (const float*)d_in[15];
    float* out = (float*)d_out;

    k_encode<<<NTOT / 32, 128>>>(x, emb);

    for (int li = 0; li < 2; li++) {
        k_agg<<<NB, 128>>>(ei);
        k_gemm<1, 0><<<NTOT / 128, 256>>>(cWl + li * 16384, cWr + li * 16384,
                                          cbl + li * 128,
                                          bng + li * 128, bnb + li * 128,
                                          bnm + li * 128, bnv + li * 128);
    }

    k_agg<<<NB, 128>>>(ei);
    k_slog<<<2048, 256>>>(aWl, abl, aWr);
    k_pool<<<NB, 128>>>(ei);

    for (int li = 2; li < 4; li++) {
        k_pmean<<<NB * 128 / 256, 256>>>();
        k_gemm<0, 1><<<NB * NCL / 128, 256>>>(cWl + li * 16384, cWr + li * 16384,
                                              cbl + li * 128,
                                              bng + li * 128, bnb + li * 128,
                                              bnm + li * 128, bnv + li * 128);
    }

    k_readout<<<NB, 128>>>(linW, linb, out);
    k_reduce<<<1, 1024>>>(out);
}